// round 10
// baseline (speedup 1.0000x reference)
#include <cuda_runtime.h>

#define PP 8
#define TT 128
#define NT 64
#define MAXB 8192

typedef unsigned long long ull;

struct Params {
  const float* feat; const float* hist; const int* relation; const int* pfl;
  const float* emb_phase; const float* w_veh; const float* b_veh;
  const float* w_hist; const float* b_hist;
  const float* gwih; const float* gwhh; const float* gbih; const float* gbhh;
  const float* w_lane; const float* b_lane; const float* emb_const;
  const float* wf; const float* bf; const float* wc; const float* bc;
  const float* wz; const float* bz; const float* wo; const float* bo;
  float* out; int B;
};

// scratch (static device memory — no allocations)
__device__ __align__(16) float4 g_xbuf[(size_t)MAXB * TT * PP];

__device__ __forceinline__ ull pk2(float v) {
  ull d; asm("mov.b64 %0, {%1, %1};" : "=l"(d) : "f"(v)); return d;
}
__device__ __forceinline__ ull pk2b(float lo, float hi) {
  ull d; asm("mov.b64 %0, {%1, %2};" : "=l"(d) : "f"(lo), "f"(hi)); return d;
}
__device__ __forceinline__ ull f2fma(ull a, ull b, ull c) {
  ull d; asm("fma.rn.f32x2 %0, %1, %2, %3;" : "=l"(d) : "l"(a), "l"(b), "l"(c)); return d;
}
__device__ __forceinline__ ull add2(ull a, ull b) {
  ull d; asm("add.rn.f32x2 %0, %1, %2;" : "=l"(d) : "l"(a), "l"(b)); return d;
}
__device__ __forceinline__ void upk(ull v, float& lo, float& hi) {
  asm("mov.b64 {%0, %1}, %2;" : "=f"(lo), "=f"(hi) : "l"(v));
}
__device__ __forceinline__ float loF(ull v) { float a, b; upk(v, a, b); return a; }
__device__ __forceinline__ float hiF(ull v) { float a, b; upk(v, a, b); return b; }
__device__ __forceinline__ float tanh_ap(float x) {
  float y; asm("tanh.approx.f32 %0, %1;" : "=f"(y) : "f"(x)); return y;
}
__device__ __forceinline__ float sigf(float v) {
  return fmaf(tanh_ap(0.5f * v), 0.5f, 0.5f);
}

// ---------------- precompute x = sigmoid(hist @ w_hist + b_hist) ----------------
__global__ __launch_bounds__(256) void precomp_x(const float* __restrict__ hist,
                                                 const float* __restrict__ w_hist,
                                                 const float* __restrict__ b_hist, int B) {
  long idx = (long)blockIdx.x * blockDim.x + threadIdx.x;   // over B*T
  if (idx >= (long)B * TT) return;
  const float4* row4 = reinterpret_cast<const float4*>(hist + idx * 24);
  float q[24];
  float4 rr;
#pragma unroll
  for (int i = 0; i < 6; i++) {
    rr = row4[i];
    q[4 * i] = rr.x; q[4 * i + 1] = rr.y; q[4 * i + 2] = rr.z; q[4 * i + 3] = rr.w;
  }
  float w[12], bb[4];
#pragma unroll
  for (int i = 0; i < 12; i++) w[i] = w_hist[i];
#pragma unroll
  for (int j = 0; j < 4; j++) bb[j] = b_hist[j];
  float4* dst = &g_xbuf[idx * PP];
#pragma unroll
  for (int p = 0; p < PP; p++) {
    float q0 = q[p], q1 = q[8 + p], q2 = q[16 + p];
    float4 x;
    x.x = sigf(fmaf(q0, w[0], fmaf(q1, w[4], fmaf(q2, w[8],  bb[0]))));
    x.y = sigf(fmaf(q0, w[1], fmaf(q1, w[5], fmaf(q2, w[9],  bb[1]))));
    x.z = sigf(fmaf(q0, w[2], fmaf(q1, w[6], fmaf(q2, w[10], bb[2]))));
    x.w = sigf(fmaf(q0, w[3], fmaf(q1, w[7], fmaf(q2, w[11], bb[3]))));
    dst[p] = x;
  }
}

// ---------------- main GRU + tail kernel ----------------
// 4 threads per (batch,lane): s = hidden half, c = reduction split.
// Each thread runs TWO independent batch chains (ch=0,1) sharing the same
// 112 weight registers — ILP-2 to fill the shfl/MUFU latency chain.
// Warp = 2 batches; block = 2 warps = 4 batches.
__global__ __launch_bounds__(NT, 4) void gru_kernel(Params pr) {
  __shared__ float embph_s[8], wveh_s[4], bveh_s[4];
  __shared__ float wlane_s[18 * 16], blane_s[16];
  __shared__ float wf_s[32 * 20], bf_s[20];
  __shared__ float wz_s[20 * 20], bz_s[20];
  __shared__ float wo_s[20];
  __shared__ float bo_s;
  __shared__ float wc_s[4 * 20], bc_s[20], embc_s[8];
  __shared__ int rel_s[56], pfl_s[PP];
  __shared__ float press_s[4 * PP * 17];
  __shared__ float v_s[4 * PP * 21];

  const int tid = threadIdx.x;
  const int wid  = tid >> 5;
  const int p    = (tid >> 2) & 7;
  const int s    = (tid >> 1) & 1;
  const int cbit = tid & 1;
  const bool c0  = (cbit == 0);
  const int tq   = tid & 3;

  // stage 0: tail weights -> smem
  if (tid < 8) embph_s[tid] = pr.emb_phase[tid];
  if (tid < 4) { wveh_s[tid] = pr.w_veh[tid]; bveh_s[tid] = pr.b_veh[tid]; }
  for (int i = tid; i < 288; i += NT) wlane_s[i] = pr.w_lane[i];
  if (tid < 16) blane_s[tid] = pr.b_lane[tid];
  for (int i = tid; i < 640; i += NT) wf_s[i] = pr.wf[i];
  if (tid < 20) bf_s[tid] = pr.bf[tid];
  for (int i = tid; i < 400; i += NT) wz_s[i] = pr.wz[i];
  if (tid < 20) bz_s[tid] = pr.bz[tid];
  if (tid < 20) wo_s[tid] = pr.wo[tid];
  if (tid == 0) bo_s = pr.bo[0];
  for (int i = tid; i < 80; i += NT) wc_s[i] = pr.wc[i];
  if (tid < 20) bc_s[tid] = pr.bc[tid];
  if (tid < 8) embc_s[tid] = pr.emb_const[tid];
  if (tid < 56) rel_s[tid] = pr.relation[tid];
  if (tid < PP) pfl_s[tid] = pr.pfl[tid];

  long bch[2]; bool act[2]; long bcl[2];
#pragma unroll
  for (int ch = 0; ch < 2; ch++) {
    bch[ch] = (long)blockIdx.x * 4 + 2 * wid + ch;
    act[ch] = (bch[ch] < (long)pr.B);
    bcl[ch] = act[ch] ? bch[ch] : (long)(pr.B - 1);
  }

  // ---- in-kernel weight gather: 56 loop-resident ull regs per thread ----
  const float* gwih = pr.gwih;
  const float* gwhh = pr.gwhh;
  auto wat = [&](int kk, int pos) -> float {
    if (pos >= 15) return 0.f;
    int grow;
    if (pos < 10) { int j = pos >> 1, g = pos & 1; grow = g * 10 + 5 * s + j; }
    else          { grow = 20 + 5 * s + (pos - 10); }
    if (c0) {
      if (kk < 4) return gwih[grow * 4 + kk];
      return gwhh[grow * 10 + 5 * s + (kk - 4)];
    } else {
      int hcol = (kk < 2) ? (5 * s + 3 + kk) : (5 * (1 - s) + (kk - 2));
      return gwhh[grow * 10 + hcol];
    }
  };
  ull w[7][8];
#pragma unroll
  for (int kk = 0; kk < 7; kk++)
#pragma unroll
    for (int i = 0; i < 8; i++)
      w[kk][i] = pk2b(wat(kk, 2 * i), wat(kk, 2 * i + 1));

  auto bat = [&](int pos) -> float {
    if (!c0) return 0.f;
    if (pos < 10) { int j = pos >> 1, g = pos & 1; int grow = g * 10 + 5 * s + j;
                    return pr.gbih[grow] + pr.gbhh[grow]; }
    if (pos >= 10 && pos < 15) return pr.gbih[20 + 5 * s + (pos - 10)];  // P (bih_n)
    if (pos >= 16 && pos < 21) return pr.gbhh[20 + 5 * s + (pos - 16)];  // Q (bhh_n)
    return 0.f;
  };
  ull bias[11];
#pragma unroll
  for (int i = 0; i < 11; i++) bias[i] = pk2b(bat(2 * i), bat(2 * i + 1));

  __syncthreads();

  // per-chain state
  float hO[2][3];
  float hx[2][5];
  float4 xq[2];
  const float4* xp[2];
#pragma unroll
  for (int ch = 0; ch < 2; ch++) {
#pragma unroll
    for (int j = 0; j < 3; j++) hO[ch][j] = 0.f;
#pragma unroll
    for (int j = 0; j < 5; j++) hx[ch][j] = 0.f;
    xp[ch] = &g_xbuf[bcl[ch] * TT * PP + p];
    xq[ch] = xp[ch][0];
  }

  for (int t = 0; t < TT; t++) {
    float4 xn[2];
#pragma unroll
    for (int ch = 0; ch < 2; ch++) {
      xn[ch] = make_float4(0.f, 0.f, 0.f, 0.f);
      if (t + 1 < TT) xn[ch] = xp[ch][(t + 1) * PP];
    }

    // ---- FMA blocks (both chains, shared weights) ----
    ull A[2][11];
#pragma unroll
    for (int ch = 0; ch < 2; ch++) {
      float vals[7];
      vals[0] = c0 ? xq[ch].x : hO[ch][0];
      vals[1] = c0 ? xq[ch].y : hO[ch][1];
      vals[2] = c0 ? xq[ch].z : hx[ch][0];
      vals[3] = c0 ? xq[ch].w : hx[ch][1];
      vals[4] = c0 ? hO[ch][0] : hx[ch][2];
      vals[5] = c0 ? hO[ch][1] : hx[ch][3];
      vals[6] = c0 ? hO[ch][2] : hx[ch][4];

      {
        ull s2 = pk2(vals[0]);
#pragma unroll
        for (int i = 0; i < 5; i++) A[ch][i] = f2fma(s2, w[0][i], bias[i]);
#pragma unroll
        for (int i = 0; i < 3; i++) A[ch][5 + i] = f2fma(s2, w[0][5 + i], bias[5 + i]);
        A[ch][8] = bias[8]; A[ch][9] = bias[9]; A[ch][10] = bias[10];
      }
#pragma unroll
      for (int kk = 1; kk < 7; kk++) {
        ull s2 = pk2(vals[kk]);
#pragma unroll
        for (int i = 0; i < 5; i++) A[ch][i] = f2fma(s2, w[kk][i], A[ch][i]);
        const int nb = (kk < 4) ? 5 : 8;
#pragma unroll
        for (int i = 0; i < 3; i++) A[ch][nb + i] = f2fma(s2, w[kk][5 + i], A[ch][nb + i]);
      }
    }

    // ---- exchange + combine (both chains) ----
    ull rz0[2], rz1[2], rz2[2];
    float gA[2], hA[2], gB[2], hB[2], gC[2], hC[2];
#pragma unroll
    for (int ch = 0; ch < 2; ch++) {
      ull S0 = add2(A[ch][5], A[ch][8]);
      ull S1 = add2(A[ch][6], A[ch][9]);
      ull S2 = add2(A[ch][7], A[ch][10]);

      ull r1 = __shfl_xor_sync(0xffffffffu, c0 ? A[ch][3]  : A[ch][0], 1);
      ull r2 = __shfl_xor_sync(0xffffffffu, c0 ? A[ch][4]  : A[ch][1], 1);
      ull r3 = __shfl_xor_sync(0xffffffffu, c0 ? A[ch][6]  : A[ch][2], 1);
      ull r4 = __shfl_xor_sync(0xffffffffu, c0 ? A[ch][7]  : S0,   1);
      ull r5 = __shfl_xor_sync(0xffffffffu, c0 ? A[ch][9]  : S1,   1);
      ull r6 = __shfl_xor_sync(0xffffffffu, c0 ? A[ch][10] : S2,   1);

      rz0[ch] = add2(c0 ? A[ch][0] : A[ch][3], r1);
      rz1[ch] = add2(c0 ? A[ch][1] : A[ch][4], r2);
      rz2[ch] = add2(A[ch][2], r3);
      ull hnp0 = add2(r4, A[ch][8]);
      ull hnp1 = add2(r5, A[ch][9]);

      gA[ch] = c0 ? loF(A[ch][5]) : hiF(r3);
      hA[ch] = c0 ? loF(hnp0) : (hiF(S1) + hiF(r5));
      gB[ch] = c0 ? hiF(A[ch][5]) : loF(r4);
      hB[ch] = c0 ? hiF(hnp0) : (loF(S2) + loF(r6));
      gC[ch] = loF(A[ch][6]);
      hC[ch] = loF(hnp1);
    }

    // ---- activations + h update (both chains) ----
#pragma unroll
    for (int ch = 0; ch < 2; ch++) {
      float rl, zl;
      upk(rz0[ch], rl, zl);
      float rr0 = sigf(rl), zz0 = sigf(zl);
      float nn0 = tanh_ap(fmaf(rr0, hA[ch], gA[ch]));
      upk(rz1[ch], rl, zl);
      float rr1 = sigf(rl), zz1 = sigf(zl);
      float nn1 = tanh_ap(fmaf(rr1, hB[ch], gB[ch]));
      upk(rz2[ch], rl, zl);
      float rr2 = sigf(rl), zz2 = sigf(zl);
      float nn2 = tanh_ap(fmaf(rr2, hC[ch], gC[ch]));
      hO[ch][0] = fmaf(zz0, hO[ch][0] - nn0, nn0);
      hO[ch][1] = fmaf(zz1, hO[ch][1] - nn1, nn1);
      hO[ch][2] = fmaf(zz2, hO[ch][2] - nn2, nn2);   // c1: garbage, never consumed
    }

    // ---- redistribution (both chains) ----
#pragma unroll
    for (int ch = 0; ch < 2; ch++) {
      float w3a = __shfl_xor_sync(0xffffffffu, hO[ch][0], 3);
      float w3b = __shfl_xor_sync(0xffffffffu, hO[ch][1], 3);
      float w3c = __shfl_xor_sync(0xffffffffu, hO[ch][2], 3);
      float w2a = __shfl_xor_sync(0xffffffffu, hO[ch][0], 2);
      float w2b = __shfl_xor_sync(0xffffffffu, hO[ch][1], 2);
      hx[ch][0] = w3a; hx[ch][1] = w3b; hx[ch][2] = w3c; hx[ch][3] = w2a; hx[ch][4] = w2b;
      xq[ch] = xn[ch];
    }
  }

  // ---- tail per chain: reassemble h -> pressure -> pair network ----
#pragma unroll 1
  for (int ch = 0; ch < 2; ch++) {
    float ha[10];
    {
      float t1 = __shfl_xor_sync(0xffffffffu, hO[ch][0], 1);
      float t2 = __shfl_xor_sync(0xffffffffu, hO[ch][1], 1);
      float t3 = __shfl_xor_sync(0xffffffffu, hO[ch][2], 1);
      float hf0 = c0 ? hO[ch][0] : t1;
      float hf1 = c0 ? hO[ch][1] : t2;
      float hf2 = c0 ? hO[ch][2] : t3;
      float hf3 = c0 ? t1 : hO[ch][0];
      float hf4 = c0 ? t2 : hO[ch][1];
      float hg0 = __shfl_xor_sync(0xffffffffu, hf0, 2);
      float hg1 = __shfl_xor_sync(0xffffffffu, hf1, 2);
      float hg2 = __shfl_xor_sync(0xffffffffu, hf2, 2);
      float hg3 = __shfl_xor_sync(0xffffffffu, hf3, 2);
      float hg4 = __shfl_xor_sync(0xffffffffu, hf4, 2);
      float hf[5] = {hf0, hf1, hf2, hf3, hf4};
      float hg[5] = {hg0, hg1, hg2, hg3, hg4};
#pragma unroll
      for (int j = 0; j < 5; j++) {
        ha[j]     = (s == 0) ? hf[j] : hg[j];
        ha[5 + j] = (s == 0) ? hg[j] : hf[j];
      }
    }

    const int bidx = 2 * wid + ch;
    {
      float lf[18];
      float veh = pr.feat[bcl[ch] * 16 + 8 + p];
      int pidx = (int)pr.feat[bcl[ch] * 16 + p];
#pragma unroll
      for (int j = 0; j < 4; j++) lf[j] = sigf(fmaf(veh, wveh_s[j], bveh_s[j]));
#pragma unroll
      for (int j = 0; j < 4; j++) lf[4 + j] = sigf(embph_s[pidx * 4 + j]);
#pragma unroll
      for (int i = 0; i < 10; i++) lf[8 + i] = ha[i];

      const int lrow = bidx * 8 + p;
#pragma unroll
      for (int mm = 0; mm < 4; mm++) {
        int m = 4 * tq + mm;
        float acc = blane_s[m];
#pragma unroll
        for (int k = 0; k < 18; k++) acc = fmaf(lf[k], wlane_s[k * 16 + m], acc);
        press_s[lrow * 17 + m] = 2.0f * fmaxf(acc, 0.f);
      }
      __syncwarp();
      float pf[16];
#pragma unroll
      for (int k = 0; k < 16; k++) pf[k] = press_s[lrow * 17 + k];
#pragma unroll
      for (int mm = 0; mm < 5; mm++) {
        int m = 5 * tq + mm;
        float acc = 0.f;
#pragma unroll
        for (int k = 0; k < 16; k++) acc = fmaf(pf[k], wf_s[(16 + k) * 20 + m], acc);
        v_s[lrow * 21 + m] = acc;
      }
      __syncwarp();
    }
    {
      const int iph = p;
      const int li = pfl_s[iph];
      const float* pi = &press_s[(bidx * 8 + li) * 17];

      float u[20];
#pragma unroll
      for (int m = 0; m < 20; m++) u[m] = bf_s[m];
#pragma unroll
      for (int k = 0; k < 16; k++) {
        float sv = pi[k];
#pragma unroll
        for (int m = 0; m < 20; m++) u[m] = fmaf(sv, wf_s[k * 20 + m], u[m]);
      }

      float acc = 0.f;
      const int jpS = tq * 2;
      const int jpN = (tq == 3) ? 1 : 2;
      for (int q = 0; q < jpN; q++) {
        int jp = jpS + q;
        int j = jp + (jp >= iph ? 1 : 0);
        int lj = pfl_s[j];
        const float* vj = &v_s[(bidx * 8 + lj) * 21];
        int rel = rel_s[iph * 7 + jp];
        const float* e = &embc_s[rel * 4];
        float ttv[20];
#pragma unroll
        for (int m = 0; m < 20; m++) {
          float y = bc_s[m];
#pragma unroll
          for (int c = 0; c < 4; c++) y = fmaf(e[c], wc_s[c * 20 + m], y);
          y = fmaxf(y, 0.f);
          ttv[m] = fmaxf(u[m] + vj[m], 0.f) * y;
        }
        float z2[20];
#pragma unroll
        for (int m = 0; m < 20; m++) z2[m] = bz_s[m];
#pragma unroll
        for (int m = 0; m < 20; m++) {
          float sv = ttv[m];
#pragma unroll
          for (int m2 = 0; m2 < 20; m2++) z2[m2] = fmaf(sv, wz_s[m * 20 + m2], z2[m2]);
        }
        float zs = bo_s;
#pragma unroll
        for (int m2 = 0; m2 < 20; m2++) zs = fmaf(fmaxf(z2[m2], 0.f), wo_s[m2], zs);
        acc += zs;
      }
      acc += __shfl_xor_sync(0xffffffffu, acc, 1);
      acc += __shfl_xor_sync(0xffffffffu, acc, 2);
      if (tq == 0 && act[ch]) pr.out[bch[ch] * PP + iph] = acc;
    }
    __syncwarp();
  }
}

extern "C" void kernel_launch(void* const* d_in, const int* in_sizes, int n_in,
                              void* d_out, int out_size) {
  Params pr;
  pr.feat      = (const float*)d_in[0];
  pr.hist      = (const float*)d_in[1];
  pr.relation  = (const int*)  d_in[2];
  pr.pfl       = (const int*)  d_in[3];
  pr.emb_phase = (const float*)d_in[4];
  pr.w_veh     = (const float*)d_in[5];
  pr.b_veh     = (const float*)d_in[6];
  pr.w_hist    = (const float*)d_in[7];
  pr.b_hist    = (const float*)d_in[8];
  pr.gwih      = (const float*)d_in[9];
  pr.gwhh      = (const float*)d_in[10];
  pr.gbih      = (const float*)d_in[11];
  pr.gbhh      = (const float*)d_in[12];
  pr.w_lane    = (const float*)d_in[13];
  pr.b_lane    = (const float*)d_in[14];
  pr.emb_const = (const float*)d_in[15];
  pr.wf        = (const float*)d_in[16];
  pr.bf        = (const float*)d_in[17];
  pr.wc        = (const float*)d_in[18];
  pr.bc        = (const float*)d_in[19];
  pr.wz        = (const float*)d_in[20];
  pr.bz        = (const float*)d_in[21];
  pr.wo        = (const float*)d_in[22];
  pr.bo        = (const float*)d_in[23];
  pr.out       = (float*)d_out;
  pr.B         = in_sizes[0] / (2 * PP);

  long bt = (long)pr.B * TT;
  precomp_x<<<(int)((bt + 255) / 256), 256>>>(pr.hist, pr.w_hist, pr.b_hist, pr.B);
  int grid = (pr.B + 3) / 4;
  gru_kernel<<<grid, NT>>>(pr);
}